// round 17
// baseline (speedup 1.0000x reference)
#include <cuda_runtime.h>

// AnnularDilatedKNN: B=4, N=4096, C=64, SAMPLE=16, DILATED_RATE=2 -> NSAMPLE=32, K_out=16
// radius^2 = 256.
//
// R17 = R16 with the feature gather rebuilt as an smem-staged transpose:
//  - block = 64 rows (4 consecutive n x 16 k). Phase 1: warp-loads cover 2 FULL
//    256B rows each (2 wf/row, redundancy eliminated); scatter to channel-major
//    smem (stride 65 -> <=2-way conflicts). Phase 2: pack 4 rows/channel into
//    float4, contiguous 256B stores per channel (2 wf/row = line minimum).
//    6 -> 4 wavefronts/row total; same values to same addresses.
//  - xyz gather branch, query, build, selection byte-identical to R16 winner.

#define NB     4
#define NP     4096
#define KOUT   16
#define NCY    40
#define NCZ    40
#define NCELL2 (NCY * NCZ)          // 1600
#define CMIN   (-170.0f)
#define INVC   (1.0f / 8.5f)
#define QW     16                   // warps (queries) per query block
#define SBLK   64                   // scatter blocks (256 thr), 16 per batch

__device__ float4 g_cand[NB * NP];           // cell-sorted (x,y,z,sq)
__device__ int    g_sid[NB * NP];            // original index per sorted slot
__device__ int    g_pcell[NB * NP];          // cell per original point
__device__ int    g_cstart[NB * (NCELL2 + 1)];
__device__ int    g_cursor[NB * NCELL2];
__device__ int    g_ids[NB * NP * KOUT];

__device__ __forceinline__ float sq3(float x, float y, float z) {
    // jnp.sum(xyz*xyz, -1): left-to-right, separately rounded products (no fma).
    return __fadd_rn(__fadd_rn(__fmul_rn(x, x), __fmul_rn(y, y)), __fmul_rn(z, z));
}

__device__ __forceinline__ int cell1(float v) {
    int c = (int)floorf(__fmul_rn(__fadd_rn(v, -CMIN), INVC));
    return min(max(c, 0), NCY - 1);
}

// ---- build 1: fused count + scan, one block per batch ----
__global__ __launch_bounds__(1024) void build_cs_kernel(const float* __restrict__ xyz) {
    __shared__ int cnt[NCELL2];                // 6400 B
    __shared__ int wsum[32];
    const int b = blockIdx.x, tid = threadIdx.x;
    const int lane = tid & 31, wid = tid >> 5;

    for (int k = tid; k < NCELL2; k += 1024) cnt[k] = 0;
    __syncthreads();

    #pragma unroll
    for (int j = 0; j < 4; ++j) {
        const int i = (b << 12) + tid + j * 1024;
        const float y = xyz[3 * i + 1];
        const float z = xyz[3 * i + 2];
        const int c = cell1(z) * NCY + cell1(y);
        g_pcell[i] = c;
        atomicAdd(&cnt[c], 1);
    }
    __syncthreads();

    // exclusive scan over 1600 cells: 2 cells/thread (threads 0..799)
    const int c0 = tid * 2;
    int v0 = 0, v1 = 0;
    if (c0 < NCELL2) { v0 = cnt[c0]; v1 = cnt[c0 + 1]; }
    const int s = v0 + v1;
    int incl = s;
    #pragma unroll
    for (int off = 1; off < 32; off <<= 1) {
        const int t = __shfl_up_sync(0xffffffffu, incl, off);
        if (lane >= off) incl += t;
    }
    if (lane == 31) wsum[wid] = incl;
    __syncthreads();
    if (wid == 0) {
        int wv = wsum[lane];
        int wi = wv;
        #pragma unroll
        for (int off = 1; off < 32; off <<= 1) {
            const int t = __shfl_up_sync(0xffffffffu, wi, off);
            if (lane >= off) wi += t;
        }
        wsum[lane] = wi - wv;
    }
    __syncthreads();
    if (c0 < NCELL2) {
        const int excl = (incl - s) + wsum[wid];
        g_cstart[b * (NCELL2 + 1) + c0]     = excl;
        g_cstart[b * (NCELL2 + 1) + c0 + 1] = excl + v0;
        g_cursor[b * NCELL2 + c0]     = excl;
        g_cursor[b * NCELL2 + c0 + 1] = excl + v0;
        if (c0 + 1 == NCELL2 - 1)
            g_cstart[b * (NCELL2 + 1) + NCELL2] = excl + v0 + v1;   // == NP
    }
}

// ---- build 2: scatter via global atomic cursors ----
__global__ __launch_bounds__(256) void scatter_kernel(const float* __restrict__ xyz) {
    const int i = blockIdx.x * 256 + threadIdx.x;
    const int b = i >> 12;
    const int c = g_pcell[i];
    const int pos = atomicAdd(&g_cursor[b * NCELL2 + c], 1);
    const float x = xyz[3 * i + 0];
    const float y = xyz[3 * i + 1];
    const float z = xyz[3 * i + 2];
    const int gi = (b << 12) + pos;
    g_cand[gi] = make_float4(x, y, z, sq3(x, y, z));
    g_sid[gi] = i & (NP - 1);
}

// ---- query: warp per SORTED query; 5 contiguous 2-D runs (+-2 cells) ----
__global__ __launch_bounds__(32 * QW) void query_kernel() {
    __shared__ unsigned bm[QW][128];
    __shared__ int cum[QW][128];

    const int warp = threadIdx.x >> 5, lane = threadIdx.x & 31;
    const int p = blockIdx.x * QW + warp;        // sorted position, 0..16383
    const int b = p >> 12;
    const int bb = b << 12;

    const float4 qc = g_cand[p];
    const int qn = g_sid[p];
    const float xn = qc.x, yn = qc.y, zn = qc.z, sqn = qc.w;

    const int cy = cell1(yn), cz = cell1(zn);
    const int ylo = max(cy - 2, 0), yhi = min(cy + 2, NCY - 1);
    const int zlo = max(cz - 2, 0), zhi = min(cz + 2, NCZ - 1);
    const int* __restrict__ cs = g_cstart + b * (NCELL2 + 1);

    #pragma unroll
    for (int k = 0; k < 4; ++k) bm[warp][lane * 4 + k] = 0u;
    __syncwarp();

    const float4* __restrict__ cand = g_cand + bb;
    const int* __restrict__ sid = g_sid + bb;

    for (int zz = zlo; zz <= zhi; ++zz) {
        const int st = cs[zz * NCY + ylo];
        const int e  = cs[zz * NCY + yhi + 1];
        #pragma unroll 4
        for (int i = st + lane; i < e; i += 32) {
            const float4 c = cand[i];
            // byte-identical verified predicate
            const float dot = fmaf(zn, c.z, fmaf(yn, c.y, __fmul_rn(xn, c.x)));
            const float d2  = __fsub_rn(__fadd_rn(sqn, c.w), __fmul_rn(2.0f, dot));
            if (d2 < 256.0f) {
                const int id = sid[i];
                atomicOr(&bm[warp][id >> 5], 1u << (id & 31));
            }
        }
    }
    __syncwarp();

    // verified selection: popc prefix over 128 words, ranks {0,16..30}
    int c4[4];
    int lsum = 0;
    #pragma unroll
    for (int k = 0; k < 4; ++k) {
        c4[k] = __popc(bm[warp][lane * 4 + k]);
        lsum += c4[k];
    }
    int incl = lsum;
    #pragma unroll
    for (int off = 1; off < 32; off <<= 1) {
        const int t = __shfl_up_sync(0xffffffffu, incl, off);
        if (lane >= off) incl += t;
    }
    const int cnt = __shfl_sync(0xffffffffu, incl, 31);
    int base = incl - lsum;
    #pragma unroll
    for (int k = 0; k < 4; ++k) {
        cum[warp][lane * 4 + k] = base;
        base += c4[k];
    }
    __syncwarp();

    int own = 0;
    const int t = (lane == 0) ? 0 : lane + 15;
    if (lane < 16 && t < cnt) {
        int lo = 0, hi = 127;
        while (lo < hi) {                        // largest word with cum <= t
            const int mid = (lo + hi + 1) >> 1;
            if (cum[warp][mid] <= t) lo = mid; else hi = mid - 1;
        }
        unsigned w = bm[warp][lo];
        int r = t - cum[warp][lo];
        while (r--) w &= (w - 1u);
        own = (lo << 5) + (__ffs(w) - 1);
    }
    const int h0 = __shfl_sync(0xffffffffu, own, 0);  // center (cnt>=1: self-hit)
    if (lane < 16) g_ids[((bb + qn) << 4) + lane] = (t < cnt) ? own : h0;
}

// ---- fused gather: blocks [0,256) = xyz, [256,4352) = feature transpose ----
__global__ __launch_bounds__(256) void gather_kernel(const float* __restrict__ xyz,
                                                     const float* __restrict__ feat,
                                                     float* __restrict__ out) {
    __shared__ int   s_id[64];
    __shared__ float s_t[64 * 65];               // [ch][r], stride 65 floats

    if (blockIdx.x < 256) {
        const int t  = blockIdx.x * 256 + threadIdx.x;    // b(2)|n(12)|k4(2), 65536 total
        const int k4 = t & 3;
        const int n  = (t >> 2) & (NP - 1);
        const int b  = t >> 14;
        const int bb = b << 12;
        const int4 id4 = reinterpret_cast<const int4*>(g_ids)[t];
        const int o4 = (n << 2) + k4;

        const float* xb = xyz + 3 * bb;
        const float x0 = xb[3 * id4.x], y0 = xb[3 * id4.x + 1], z0 = xb[3 * id4.x + 2];
        const float x1 = xb[3 * id4.y], y1 = xb[3 * id4.y + 1], z1 = xb[3 * id4.y + 2];
        const float x2 = xb[3 * id4.z], y2 = xb[3 * id4.z + 1], z2 = xb[3 * id4.z + 2];
        const float x3 = xb[3 * id4.w], y3 = xb[3 * id4.w + 1], z3 = xb[3 * id4.w + 2];
        float4* o = reinterpret_cast<float4*>(out);
        o[((b * 3 + 0) << 14) + o4] = make_float4(x0, x1, x2, x3);
        o[((b * 3 + 1) << 14) + o4] = make_float4(y0, y1, y2, y3);
        o[((b * 3 + 2) << 14) + o4] = make_float4(z0, z1, z2, z3);
    } else {
        // block handles 64 rows = (n0..n0+3) x k(16) of one batch
        const int g  = blockIdx.x - 256;          // 0..4095
        const int b  = g >> 10;
        const int n0 = (g & 1023) << 2;
        const int bb = b << 12;
        const int tid = threadIdx.x;

        if (tid < 64) s_id[tid] = g_ids[((bb + n0) << 4) + tid];   // row r -> id
        __syncthreads();

        // phase 1: warp-load covers 2 full 256B rows; scatter to channel-major smem
        const float4* __restrict__ f4 = reinterpret_cast<const float4*>(feat);
        #pragma unroll
        for (int p = 0; p < 4; ++p) {
            const int idx = tid + (p << 8);       // 0..1023
            const int row = idx >> 4;             // 0..63
            const int off = idx & 15;             // f4 within row
            const float4 v = f4[((bb + s_id[row]) << 4) + off];
            const int ch = off << 2;
            s_t[(ch + 0) * 65 + row] = v.x;
            s_t[(ch + 1) * 65 + row] = v.y;
            s_t[(ch + 2) * 65 + row] = v.z;
            s_t[(ch + 3) * 65 + row] = v.w;
        }
        __syncthreads();

        // phase 2: pack rows 4f..4f+3 of channel ch; contiguous 256B per channel
        float4* __restrict__ o = reinterpret_cast<float4*>(out) + ((12 + b * 64) << 14);
        #pragma unroll
        for (int p = 0; p < 4; ++p) {
            const int idx = tid + (p << 8);
            const int ch = idx >> 4;              // 0..63
            const int f  = idx & 15;              // f4 within the block's 64-float span
            const float* sr = s_t + ch * 65 + (f << 2);
            o[(ch << 14) + (n0 << 2) + f] = make_float4(sr[0], sr[1], sr[2], sr[3]);
        }
    }
}

extern "C" void kernel_launch(void* const* d_in, const int* in_sizes, int n_in,
                              void* d_out, int out_size) {
    const float* xyz  = (const float*)d_in[0];
    const float* feat = (const float*)d_in[1];
    float* out = (float*)d_out;

    build_cs_kernel<<<NB, 1024>>>(xyz);
    scatter_kernel<<<SBLK, 256>>>(xyz);
    query_kernel<<<(NB * NP) / QW, 32 * QW>>>();
    gather_kernel<<<256 + NB * (NP / 4), 256>>>(xyz, feat, out);
}